// round 13
// baseline (speedup 1.0000x reference)
#include <cuda_runtime.h>
#include <cstdint>

typedef unsigned long long u64;
typedef unsigned int u32;

#define Nn 8
#define Cc 80
#define HWp 25600
#define PER_IMG (Cc*HWp)        // 2048000
#define FINE 64
#define FINE_BASE 8089          // (SPEC_BITS >> 17)
#define CAP 4096
#define CAP_SPEC 65536
#define KP 1024
#define KK 1000
#define POST 100
#define SPEC_BITS 0x3F333333u   /* bits of 0.70f */
#define REJECT_X 0.8400f        /* conservative: sigmoid(0.84)=0.6985 < 0.70 */
#define CSTAGE 4096
#define SSTAGE 512
#define TILE_JOBS 136           /* 16*17/2 upper-triangular 64x64 tiles */

// ---------------- scratch (device globals; zero-init; counters re-zeroed by k_scanout) ----
__device__ u32   g_fine[Nn*FINE];
__device__ int   g_scnt[Nn];
__device__ int   g_fbforce[Nn];
__device__ u64   g_spec[Nn*CAP_SPEC];
__device__ float g_score[Nn*KP];
__device__ float g_boxes[Nn*KP*4];
__device__ int   g_label[Nn*KP];
__device__ u32   g_validw[Nn*32];
__device__ float g_maxo[Nn];
__device__ u64   g_mask[Nn*KP*16];

__device__ __forceinline__ float sigmoidf_(float x) {
    return 1.0f / (1.0f + expf(-x));
}

// ---------------- pass 1: stream cls, warp-aggregated compact, dense sigmoid, fine hist ----
__global__ void __launch_bounds__(256) k_hist(const float* __restrict__ cls,
                                              const float* __restrict__ ctr) {
    __shared__ float sx[CSTAGE];
    __shared__ u32   se[CSTAGE];
    __shared__ u64   stage[SSTAGE];
    __shared__ u32   fine[FINE];
    __shared__ int cstage_n, sstage_n, sbase;
    if (threadIdx.x < FINE) fine[threadIdx.x] = 0;
    if (threadIdx.x == 0) { cstage_n = 0; sstage_n = 0; }
    __syncthreads();
    int n = blockIdx.y;
    u32 lane = threadIdx.x & 31;
    u32 lt_mask = (1u << lane) - 1u;
    const float4* cls4 = (const float4*)(cls + (size_t)n*PER_IMG);
    int t4 = blockIdx.x*2048 + threadIdx.x;
    // Phase A: stream + warp-aggregated compact
    #pragma unroll
    for (int it = 0; it < 8; it++, t4 += 256) {
        float4 x = cls4[t4];
        int e = t4*4;
        float pv[4] = {x.x, x.y, x.z, x.w};
        #pragma unroll
        for (int k = 0; k < 4; k++) {
            bool pred = (pv[k] >= REJECT_X);
            u32 ballot = __ballot_sync(0xffffffffu, pred);
            if (ballot) {
                int base;
                if (lane == 0) base = atomicAdd(&cstage_n, __popc(ballot));
                base = __shfl_sync(0xffffffffu, base, 0);
                if (pred) {
                    int pos = base + __popc(ballot & lt_mask);
                    if (pos < CSTAGE) { sx[pos] = pv[k]; se[pos] = (u32)(e + k); }
                }
            }
        }
    }
    __syncthreads();
    int m = cstage_n; if (m > CSTAGE) m = CSTAGE;
    // Phase B: dense sigmoid on compacted list
    const float* ctrn = ctr + n*HWp;
    for (int i = threadIdx.x; i < m; i += 256) {
        float xv = sx[i];
        u32 e = se[i];
        u32 c = e / (u32)HWp;
        u32 pix = e - c*(u32)HWp;
        float p = sigmoidf_(xv);
        float cv = sigmoidf_(ctrn[pix]);
        float s = p*cv;
        u32 sb = __float_as_uint(s);
        if (p > 0.05f && sb >= SPEC_BITS) {
            atomicAdd(&fine[(sb >> 17) - FINE_BASE], 1u);
            u64 key = (((u64)(~sb)) << 32) | (u64)(pix*80u + c);
            int pos = atomicAdd(&sstage_n, 1);
            if (pos < SSTAGE) stage[pos] = key;
            else {
                int gp = atomicAdd(&g_scnt[n], 1);
                if (gp < CAP_SPEC) g_spec[n*CAP_SPEC + gp] = key;
            }
        }
    }
    __syncthreads();
    if (threadIdx.x < FINE) {
        u32 v = fine[threadIdx.x];
        if (v) atomicAdd(&g_fine[n*FINE + threadIdx.x], v);
    }
    int sm = sstage_n < SSTAGE ? sstage_n : SSTAGE;
    if (threadIdx.x == 0 && sm > 0) sbase = atomicAdd(&g_scnt[n], sm);
    __syncthreads();
    for (int i = threadIdx.x; i < sm; i += 256) {
        int gp = sbase + i;
        if (gp < CAP_SPEC) g_spec[n*CAP_SPEC + gp] = stage[i];
    }
    if (threadIdx.x == 0 && cstage_n > CSTAGE) g_fbforce[n] = 1;
}

// ---------------- fused threshold + filter + bitonic sort + box decode + max_c ----------
__global__ void __launch_bounds__(1024) k_sortdecode(const float* __restrict__ cls,
                                                     const float* __restrict__ ctr,
                                                     const float* __restrict__ reg,
                                                     const float* __restrict__ pts,
                                                     const float* __restrict__ imsz) {
    __shared__ u64 sk[CAP];           // reused as u32[8192] hist in parachute
    __shared__ float red[1024];
    __shared__ int cnt_s;
    __shared__ int fb_s;
    __shared__ u32 tb_s;
    int n = blockIdx.x, tid = threadIdx.x;
    // threshold from fine histogram (fast path)
    if (tid == 0) {
        u32 cum = 0; int fstar = -1;
        for (int f = FINE - 1; f >= 1; f--) {
            cum += g_fine[n*FINE + f];
            if (cum >= (u32)KK) { fstar = f; break; }
        }
        int fb = (fstar < 0) || (g_scnt[n] > CAP_SPEC) || g_fbforce[n];
        fb_s = fb;
        tb_s = fb ? 0u : (((u32)(FINE_BASE + fstar)) << 17);
        cnt_s = 0;
    }
    __syncthreads();
    if (fb_s) {
        // parachute: exact full-range histogram using sk as u32[8192]
        u32* h = (u32*)sk;
        for (int i = tid; i < 8192; i += 1024) h[i] = 0;
        __syncthreads();
        const float* c0 = cls + (size_t)n*PER_IMG;
        const float* ctrn = ctr + n*HWp;
        for (int e = tid; e < PER_IMG; e += 1024) {
            int c = e / HWp; int pix = e - c*HWp;
            float p = sigmoidf_(c0[e]);
            if (p > 0.05f) {
                float cv = sigmoidf_(ctrn[pix]);
                u32 sb = __float_as_uint(p*cv);
                atomicAdd(&h[sb >> 17], 1u);
            }
        }
        __syncthreads();
        if (tid == 0) {
            u32 cum = 0; u32 tb = 0;
            for (int b = 8191; b >= 0; b--) {
                cum += h[b];
                if (cum >= (u32)KK) { tb = ((u32)b) << 17; break; }
            }
            tb_s = tb;
        }
        __syncthreads();
    }
    for (int i = tid; i < CAP; i += 1024) sk[i] = ~0ULL;
    __syncthreads();
    u32 tb = tb_s;
    if (!fb_s) {
        int m = g_scnt[n];
        for (int i = tid; i < m; i += 1024) {
            u64 key = g_spec[n*CAP_SPEC + i];
            u32 sb = ~((u32)(key >> 32));
            if (sb >= tb) {
                int pos = atomicAdd(&cnt_s, 1);
                if (pos < CAP) sk[pos] = key;
            }
        }
    } else {
        const float* c0 = cls + (size_t)n*PER_IMG;
        const float* ctrn = ctr + n*HWp;
        for (int e = tid; e < PER_IMG; e += 1024) {
            int c = e / HWp; int pix = e - c*HWp;
            float p = sigmoidf_(c0[e]);
            if (p > 0.05f) {
                float cv = sigmoidf_(ctrn[pix]);
                float s = p*cv;
                u32 sb = __float_as_uint(s);
                if (sb >= tb) {
                    int pos = atomicAdd(&cnt_s, 1);
                    if (pos < CAP) sk[pos] = (((u64)(~sb)) << 32) | (u64)((u32)pix*80u + (u32)c);
                }
            }
        }
    }
    __syncthreads();
    int cnt = cnt_s; if (cnt > CAP) cnt = CAP;
    int S = (cnt <= 2048) ? 2048 : 4096;
    for (int k2 = 2; k2 <= S; k2 <<= 1) {
        for (int j = k2 >> 1; j > 0; j >>= 1) {
            for (int i = tid; i < S; i += 1024) {
                int p = i ^ j;
                if (p > i) {
                    u64 a = sk[i], b = sk[p];
                    bool up = ((i & k2) == 0);
                    if ((a > b) == up) { sk[i] = b; sk[p] = a; }
                }
            }
            __syncthreads();
        }
    }
    float w1 = imsz[n*2] - 1.0f;
    float h1 = imsz[n*2 + 1] - 1.0f;
    const float* rg = reg + (size_t)n*4*HWp;
    float mx = 0.0f;
    {
        int r = tid;                       // KP == blockDim == 1024
        u64 key = sk[r];
        float val; int valid; u32 idx;
        if (key == ~0ULL || r >= KK) { val = -1.0f; valid = 0; idx = 0; }
        else {
            u32 sb = ~((u32)(key >> 32));
            val = __uint_as_float(sb);
            idx = (u32)key;
            valid = (val >= 0.0f) ? 1 : 0;
        }
        u32 c = idx % 80u;
        u32 loc = idx / 80u;
        float px = pts[loc*2], py = pts[loc*2 + 1];
        float d0 = rg[loc], d1 = rg[HWp + loc], d2 = rg[2*HWp + loc], d3 = rg[3*HWp + loc];
        float x1 = fminf(fmaxf(px - d0, 0.0f), w1);
        float y1 = fminf(fmaxf(py - d1, 0.0f), h1);
        float x2 = fminf(fmaxf(px + d2, 0.0f), w1);
        float y2 = fminf(fmaxf(py + d3, 0.0f), h1);
        int o = (n*KP + r)*4;
        g_boxes[o] = x1; g_boxes[o+1] = y1; g_boxes[o+2] = x2; g_boxes[o+3] = y2;
        g_label[n*KP + r] = (int)c + 1;
        g_score[n*KP + r] = valid ? sqrtf(fmaxf(val, 0.0f)) : -1.0f;
        // valid bitmap via ballot: 32 warps x 32 lanes = 1024 entries
        u32 bal = __ballot_sync(0xffffffffu, valid != 0);
        if ((tid & 31) == 0) g_validw[n*32 + (tid >> 5)] = bal;
        mx = valid ? fmaxf(fmaxf(x1, x2), fmaxf(y1, y2)) : 0.0f;
    }
    red[tid] = mx;
    __syncthreads();
    for (int s = 512; s > 0; s >>= 1) {
        if (tid < s) red[tid] = fmaxf(red[tid], red[tid + s]);
        __syncthreads();
    }
    if (tid == 0) g_maxo[n] = red[0] + 1.0f;
}

// ---------------- dense triangular IoU tiles: 4 tile-jobs per 256-thread block ----------
__global__ void __launch_bounds__(256) k_mask() {
    int jobLocal = threadIdx.x >> 6;       // 0..3
    int t = threadIdx.x & 63;
    int job = blockIdx.x*4 + jobLocal;     // 0..1087
    int n = job / TILE_JOBS;
    int q = job - n*TILE_JOBS;
    int ti = 0;
    for (int r = 0; r < 16; r++) {
        int cnt = 16 - r;
        if (q < cnt) { ti = r; break; }
        q -= cnt;
    }
    int tj = ti + q;
    float maxo = g_maxo[n];
    int i = ti*64 + t;
    int oi = (n*KP + i)*4;
    float offi = (float)g_label[n*KP + i] * maxo;
    float ax1 = g_boxes[oi]   + offi;
    float ay1 = g_boxes[oi+1] + offi;
    float ax2 = g_boxes[oi+2] + offi;
    float ay2 = g_boxes[oi+3] + offi;
    float areai = (ax2 - ax1)*(ay2 - ay1);
    __shared__ float sb[4][64][5];
    int j0 = tj*64 + t;
    int oj = (n*KP + j0)*4;
    float offj = (float)g_label[n*KP + j0] * maxo;
    float bx1 = g_boxes[oj]   + offj;
    float by1 = g_boxes[oj+1] + offj;
    float bx2 = g_boxes[oj+2] + offj;
    float by2 = g_boxes[oj+3] + offj;
    sb[jobLocal][t][0] = bx1;
    sb[jobLocal][t][1] = by1;
    sb[jobLocal][t][2] = bx2;
    sb[jobLocal][t][3] = by2;
    sb[jobLocal][t][4] = (bx2 - bx1)*(by2 - by1);
    __syncthreads();
    u64 bits = 0;
    if (i < KK) {
        int jbase = tj*64;
        const float (*sj)[5] = sb[jobLocal];
        #pragma unroll 4
        for (int jj = 0; jj < 64; jj++) {
            int j = jbase + jj;
            if (j <= i || j >= KK) continue;
            float xx1 = fmaxf(ax1, sj[jj][0]);
            float yy1 = fmaxf(ay1, sj[jj][1]);
            float xx2 = fminf(ax2, sj[jj][2]);
            float yy2 = fminf(ay2, sj[jj][3]);
            float inter = fmaxf(xx2 - xx1, 0.0f)*fmaxf(yy2 - yy1, 0.0f);
            float den = fmaxf(areai + sj[jj][4] - inter, 1e-6f);
            if (inter / den > 0.6f) bits |= 1ull << jj;
        }
    }
    g_mask[(size_t)(n*KP + i)*16 + tj] = bits;
}

// ---------------- fused NMS scan + top-100 output + counter cleanup ----------------
// Warp-0-only scan, software-pipelined: lane t owns rem_t; per chunk the 32 column
// loads for chunk c+1 are issued BEFORE chunk c's resolve chain, hiding global
// latency behind the serial work. Diag words of chunk c live in lane c's registers.
__global__ void __launch_bounds__(256, 1) k_scanout(float* __restrict__ out, int out_size) {
    int n = blockIdx.x, t = threadIdx.x;
    __shared__ u32 keep_s[32];
    const u32* gm32 = (const u32*)g_mask;
    if (t < 32) {
        u32 rem = ~g_validw[n*32 + t];     // suppressed-or-invalid bits start set
        u32 m[32];
        {   // preload chunk 0: lane t takes word t of rows 0..31 (coalesced per row)
            const u32* rowbase = gm32 + ((size_t)(n*KP))*32 + t;
            #pragma unroll
            for (int b = 0; b < 32; b++) m[b] = rowbase[b*32];
        }
        for (int c = 0; c < 32; c++) {
            u32 mn[32];
            if (c < 31 && t >= c + 1) {
                // prefetch chunk c+1 (only lanes that will still use their column)
                const u32* rowbase = gm32 + ((size_t)(n*KP + (c + 1)*32))*32 + t;
                #pragma unroll
                for (int b = 0; b < 32; b++) mn[b] = rowbase[b*32];
            }
            if (t == c) {
                // lane c holds this chunk's diag words in m[]: serial resolve in regs
                u32 rcur = rem, kb = 0;
                #pragma unroll
                for (int b = 0; b < 32; b++) {
                    u32 dead = (u32)(((int)(rcur << (31 - b))) >> 31); // all-ones if bit b set
                    kb |= ~dead & (1u << b);
                    rcur |= m[b] & ~dead;
                }
                rem = rcur;
                keep_s[c] = kb;
            }
            __syncwarp();
            u32 kb = keep_s[c];
            if (t > c) {
                #pragma unroll
                for (int b = 0; b < 32; b++) {
                    u32 sel = 0u - ((kb >> b) & 1u);
                    rem |= m[b] & sel;
                }
                #pragma unroll
                for (int b = 0; b < 32; b++) m[b] = mn[b];
            }
            __syncwarp();
        }
    }
    __syncthreads();
    __shared__ int offs[32], noffs[32];
    __shared__ int cnts[32], ncnts[32];
    __shared__ int list[POST];
    __shared__ int mks;
    if (t < 32) {
        u32 vmask = (t == 31) ? 0xFFu : 0xFFFFFFFFu;   // bits i < 1000
        cnts[t]  = __popc(keep_s[t]);
        ncnts[t] = __popc(~keep_s[t] & vmask);
    }
    __syncthreads();
    if (t == 0) {
        int acc = 0;
        for (int w = 0; w < 32; w++) { offs[w] = acc; acc += cnts[w]; }
        mks = acc > POST ? POST : acc;
        int acc2 = 0;
        for (int w = 0; w < 32; w++) { noffs[w] = acc2; acc2 += ncnts[w]; }
    }
    __syncthreads();
    if (t < 32) {
        u32 w = keep_s[t];
        int off = offs[t];
        while (w && off < POST) { int b = __ffs(w) - 1; list[off++] = t*32 + b; w &= w - 1; }
        u32 vmask = (t == 31) ? 0xFFu : 0xFFFFFFFFu;
        u32 nw = ~keep_s[t] & vmask;
        int noff = mks + noffs[t];
        while (nw && noff < POST) { int b = __ffs(nw) - 1; list[noff++] = t*32 + b; nw &= nw - 1; }
    }
    __syncthreads();
    if (t < POST) {
        int j = list[t];
        bool ov = t < mks;
        int ob = (n*KP + j)*4;
        int base = n*POST*5 + t*5;
        if (base + 4 < out_size) {
            out[base]     = g_boxes[ob];
            out[base + 1] = g_boxes[ob + 1];
            out[base + 2] = g_boxes[ob + 2];
            out[base + 3] = g_boxes[ob + 3];
            out[base + 4] = ov ? g_score[n*KP + j] : 0.0f;
        }
        int lb = Nn*POST*5 + n*POST + t;
        if (lb < out_size) out[lb] = ov ? (float)g_label[n*KP + j] : 0.0f;
        int vb = Nn*POST*5 + Nn*POST + n*POST + t;
        if (vb < out_size) out[vb] = ov ? 1.0f : 0.0f;
    }
    // cleanup for next graph replay (deterministic: zero before, zero after)
    if (t >= 128 && t < 128 + FINE) g_fine[n*FINE + (t - 128)] = 0u;
    if (t == 224) { g_scnt[n] = 0; g_fbforce[n] = 0; }
}

extern "C" void kernel_launch(void* const* d_in, const int* in_sizes, int n_in,
                              void* d_out, int out_size) {
    const float* cls  = (const float*)d_in[0];
    const float* reg  = (const float*)d_in[1];
    const float* ctr  = (const float*)d_in[2];
    const float* pts  = (const float*)d_in[3];
    const float* imsz = (const float*)d_in[4];

    k_hist<<<dim3(250, 8), 256>>>(cls, ctr);
    k_sortdecode<<<8, 1024>>>(cls, ctr, reg, pts, imsz);
    k_mask<<<272, 256>>>();
    k_scanout<<<8, 256>>>((float*)d_out, out_size);
}

// round 14
// speedup vs baseline: 1.0357x; 1.0357x over previous
#include <cuda_runtime.h>
#include <cstdint>

typedef unsigned long long u64;
typedef unsigned int u32;

#define Nn 8
#define Cc 80
#define HWp 25600
#define PER_IMG (Cc*HWp)        // 2048000
#define FINE 64
#define FINE_BASE 8089          // (SPEC_BITS >> 17)
#define CAP 4096
#define CAP_SPEC 65536
#define KP 1024
#define KK 1000
#define POST 100
#define SPEC_BITS 0x3F333333u   /* bits of 0.70f */
#define REJECT_X 0.8400f        /* conservative: sigmoid(0.84)=0.6985 < 0.70 */
#define CSTAGE 4096
#define SSTAGE 512
#define TILE_JOBS 136           /* 16*17/2 upper-triangular 64x64 tiles */

// ---------------- scratch (device globals; zero-init; counters re-zeroed by k_scanout) ----
__device__ u32   g_fine[Nn*FINE];
__device__ int   g_scnt[Nn];
__device__ int   g_fbforce[Nn];
__device__ u64   g_spec[Nn*CAP_SPEC];
__device__ float g_score[Nn*KP];
__device__ float g_boxes[Nn*KP*4];
__device__ int   g_label[Nn*KP];
__device__ u32   g_validw[Nn*32];
__device__ float g_maxo[Nn];
__device__ u64   g_mask[Nn*KP*16];

__device__ __forceinline__ float sigmoidf_(float x) {
    return 1.0f / (1.0f + expf(-x));
}

// ---------------- pass 1: stream cls, warp-aggregated compact, dense sigmoid, fine hist ----
__global__ void __launch_bounds__(256) k_hist(const float* __restrict__ cls,
                                              const float* __restrict__ ctr) {
    __shared__ float sx[CSTAGE];
    __shared__ u32   se[CSTAGE];
    __shared__ u64   stage[SSTAGE];
    __shared__ u32   fine[FINE];
    __shared__ int cstage_n, sstage_n, sbase;
    if (threadIdx.x < FINE) fine[threadIdx.x] = 0;
    if (threadIdx.x == 0) { cstage_n = 0; sstage_n = 0; }
    __syncthreads();
    int n = blockIdx.y;
    u32 lane = threadIdx.x & 31;
    u32 lt_mask = (1u << lane) - 1u;
    const float4* cls4 = (const float4*)(cls + (size_t)n*PER_IMG);
    int t4 = blockIdx.x*2048 + threadIdx.x;
    // Phase A: stream + warp-aggregated compact
    #pragma unroll
    for (int it = 0; it < 8; it++, t4 += 256) {
        float4 x = cls4[t4];
        int e = t4*4;
        float pv[4] = {x.x, x.y, x.z, x.w};
        #pragma unroll
        for (int k = 0; k < 4; k++) {
            bool pred = (pv[k] >= REJECT_X);
            u32 ballot = __ballot_sync(0xffffffffu, pred);
            if (ballot) {
                int base;
                if (lane == 0) base = atomicAdd(&cstage_n, __popc(ballot));
                base = __shfl_sync(0xffffffffu, base, 0);
                if (pred) {
                    int pos = base + __popc(ballot & lt_mask);
                    if (pos < CSTAGE) { sx[pos] = pv[k]; se[pos] = (u32)(e + k); }
                }
            }
        }
    }
    __syncthreads();
    int m = cstage_n; if (m > CSTAGE) m = CSTAGE;
    // Phase B: dense sigmoid on compacted list
    const float* ctrn = ctr + n*HWp;
    for (int i = threadIdx.x; i < m; i += 256) {
        float xv = sx[i];
        u32 e = se[i];
        u32 c = e / (u32)HWp;
        u32 pix = e - c*(u32)HWp;
        float p = sigmoidf_(xv);
        float cv = sigmoidf_(ctrn[pix]);
        float s = p*cv;
        u32 sb = __float_as_uint(s);
        if (p > 0.05f && sb >= SPEC_BITS) {
            atomicAdd(&fine[(sb >> 17) - FINE_BASE], 1u);
            u64 key = (((u64)(~sb)) << 32) | (u64)(pix*80u + c);
            int pos = atomicAdd(&sstage_n, 1);
            if (pos < SSTAGE) stage[pos] = key;
            else {
                int gp = atomicAdd(&g_scnt[n], 1);
                if (gp < CAP_SPEC) g_spec[n*CAP_SPEC + gp] = key;
            }
        }
    }
    __syncthreads();
    if (threadIdx.x < FINE) {
        u32 v = fine[threadIdx.x];
        if (v) atomicAdd(&g_fine[n*FINE + threadIdx.x], v);
    }
    int sm = sstage_n < SSTAGE ? sstage_n : SSTAGE;
    if (threadIdx.x == 0 && sm > 0) sbase = atomicAdd(&g_scnt[n], sm);
    __syncthreads();
    for (int i = threadIdx.x; i < sm; i += 256) {
        int gp = sbase + i;
        if (gp < CAP_SPEC) g_spec[n*CAP_SPEC + gp] = stage[i];
    }
    if (threadIdx.x == 0 && cstage_n > CSTAGE) g_fbforce[n] = 1;
}

// ---------------- fused threshold + filter + bitonic sort + box decode + max_c ----------
__global__ void __launch_bounds__(1024) k_sortdecode(const float* __restrict__ cls,
                                                     const float* __restrict__ ctr,
                                                     const float* __restrict__ reg,
                                                     const float* __restrict__ pts,
                                                     const float* __restrict__ imsz) {
    __shared__ u64 sk[CAP];           // reused as u32[8192] hist in parachute
    __shared__ float red[1024];
    __shared__ int cnt_s;
    __shared__ int fb_s;
    __shared__ u32 tb_s;
    int n = blockIdx.x, tid = threadIdx.x;
    // threshold from fine histogram (fast path)
    if (tid == 0) {
        u32 cum = 0; int fstar = -1;
        for (int f = FINE - 1; f >= 1; f--) {
            cum += g_fine[n*FINE + f];
            if (cum >= (u32)KK) { fstar = f; break; }
        }
        int fb = (fstar < 0) || (g_scnt[n] > CAP_SPEC) || g_fbforce[n];
        fb_s = fb;
        tb_s = fb ? 0u : (((u32)(FINE_BASE + fstar)) << 17);
        cnt_s = 0;
    }
    __syncthreads();
    if (fb_s) {
        // parachute: exact full-range histogram using sk as u32[8192]
        u32* h = (u32*)sk;
        for (int i = tid; i < 8192; i += 1024) h[i] = 0;
        __syncthreads();
        const float* c0 = cls + (size_t)n*PER_IMG;
        const float* ctrn = ctr + n*HWp;
        for (int e = tid; e < PER_IMG; e += 1024) {
            int c = e / HWp; int pix = e - c*HWp;
            float p = sigmoidf_(c0[e]);
            if (p > 0.05f) {
                float cv = sigmoidf_(ctrn[pix]);
                u32 sb = __float_as_uint(p*cv);
                atomicAdd(&h[sb >> 17], 1u);
            }
        }
        __syncthreads();
        if (tid == 0) {
            u32 cum = 0; u32 tb = 0;
            for (int b = 8191; b >= 0; b--) {
                cum += h[b];
                if (cum >= (u32)KK) { tb = ((u32)b) << 17; break; }
            }
            tb_s = tb;
        }
        __syncthreads();
    }
    for (int i = tid; i < CAP; i += 1024) sk[i] = ~0ULL;
    __syncthreads();
    u32 tb = tb_s;
    if (!fb_s) {
        int m = g_scnt[n];
        for (int i = tid; i < m; i += 1024) {
            u64 key = g_spec[n*CAP_SPEC + i];
            u32 sb = ~((u32)(key >> 32));
            if (sb >= tb) {
                int pos = atomicAdd(&cnt_s, 1);
                if (pos < CAP) sk[pos] = key;
            }
        }
    } else {
        const float* c0 = cls + (size_t)n*PER_IMG;
        const float* ctrn = ctr + n*HWp;
        for (int e = tid; e < PER_IMG; e += 1024) {
            int c = e / HWp; int pix = e - c*HWp;
            float p = sigmoidf_(c0[e]);
            if (p > 0.05f) {
                float cv = sigmoidf_(ctrn[pix]);
                float s = p*cv;
                u32 sb = __float_as_uint(s);
                if (sb >= tb) {
                    int pos = atomicAdd(&cnt_s, 1);
                    if (pos < CAP) sk[pos] = (((u64)(~sb)) << 32) | (u64)((u32)pix*80u + (u32)c);
                }
            }
        }
    }
    __syncthreads();
    int cnt = cnt_s; if (cnt > CAP) cnt = CAP;
    int S = (cnt <= 2048) ? 2048 : 4096;
    for (int k2 = 2; k2 <= S; k2 <<= 1) {
        for (int j = k2 >> 1; j > 0; j >>= 1) {
            for (int i = tid; i < S; i += 1024) {
                int p = i ^ j;
                if (p > i) {
                    u64 a = sk[i], b = sk[p];
                    bool up = ((i & k2) == 0);
                    if ((a > b) == up) { sk[i] = b; sk[p] = a; }
                }
            }
            __syncthreads();
        }
    }
    float w1 = imsz[n*2] - 1.0f;
    float h1 = imsz[n*2 + 1] - 1.0f;
    const float* rg = reg + (size_t)n*4*HWp;
    float mx = 0.0f;
    {
        int r = tid;                       // KP == blockDim == 1024
        u64 key = sk[r];
        float val; int valid; u32 idx;
        if (key == ~0ULL || r >= KK) { val = -1.0f; valid = 0; idx = 0; }
        else {
            u32 sb = ~((u32)(key >> 32));
            val = __uint_as_float(sb);
            idx = (u32)key;
            valid = (val >= 0.0f) ? 1 : 0;
        }
        u32 c = idx % 80u;
        u32 loc = idx / 80u;
        float px = pts[loc*2], py = pts[loc*2 + 1];
        float d0 = rg[loc], d1 = rg[HWp + loc], d2 = rg[2*HWp + loc], d3 = rg[3*HWp + loc];
        float x1 = fminf(fmaxf(px - d0, 0.0f), w1);
        float y1 = fminf(fmaxf(py - d1, 0.0f), h1);
        float x2 = fminf(fmaxf(px + d2, 0.0f), w1);
        float y2 = fminf(fmaxf(py + d3, 0.0f), h1);
        int o = (n*KP + r)*4;
        g_boxes[o] = x1; g_boxes[o+1] = y1; g_boxes[o+2] = x2; g_boxes[o+3] = y2;
        g_label[n*KP + r] = (int)c + 1;
        g_score[n*KP + r] = valid ? sqrtf(fmaxf(val, 0.0f)) : -1.0f;
        // valid bitmap via ballot: 32 warps x 32 lanes = 1024 entries
        u32 bal = __ballot_sync(0xffffffffu, valid != 0);
        if ((tid & 31) == 0) g_validw[n*32 + (tid >> 5)] = bal;
        mx = valid ? fmaxf(fmaxf(x1, x2), fmaxf(y1, y2)) : 0.0f;
    }
    red[tid] = mx;
    __syncthreads();
    for (int s = 512; s > 0; s >>= 1) {
        if (tid < s) red[tid] = fmaxf(red[tid], red[tid + s]);
        __syncthreads();
    }
    if (tid == 0) g_maxo[n] = red[0] + 1.0f;
}

// ---------------- dense triangular IoU tiles: 4 tile-jobs per 256-thread block ----------
__global__ void __launch_bounds__(256) k_mask() {
    int jobLocal = threadIdx.x >> 6;       // 0..3
    int t = threadIdx.x & 63;
    int job = blockIdx.x*4 + jobLocal;     // 0..1087
    int n = job / TILE_JOBS;
    int q = job - n*TILE_JOBS;
    int ti = 0;
    for (int r = 0; r < 16; r++) {
        int cnt = 16 - r;
        if (q < cnt) { ti = r; break; }
        q -= cnt;
    }
    int tj = ti + q;
    float maxo = g_maxo[n];
    int i = ti*64 + t;
    int oi = (n*KP + i)*4;
    float offi = (float)g_label[n*KP + i] * maxo;
    float ax1 = g_boxes[oi]   + offi;
    float ay1 = g_boxes[oi+1] + offi;
    float ax2 = g_boxes[oi+2] + offi;
    float ay2 = g_boxes[oi+3] + offi;
    float areai = (ax2 - ax1)*(ay2 - ay1);
    __shared__ float sb[4][64][5];
    int j0 = tj*64 + t;
    int oj = (n*KP + j0)*4;
    float offj = (float)g_label[n*KP + j0] * maxo;
    float bx1 = g_boxes[oj]   + offj;
    float by1 = g_boxes[oj+1] + offj;
    float bx2 = g_boxes[oj+2] + offj;
    float by2 = g_boxes[oj+3] + offj;
    sb[jobLocal][t][0] = bx1;
    sb[jobLocal][t][1] = by1;
    sb[jobLocal][t][2] = bx2;
    sb[jobLocal][t][3] = by2;
    sb[jobLocal][t][4] = (bx2 - bx1)*(by2 - by1);
    __syncthreads();
    u64 bits = 0;
    if (i < KK) {
        int jbase = tj*64;
        const float (*sj)[5] = sb[jobLocal];
        #pragma unroll 4
        for (int jj = 0; jj < 64; jj++) {
            int j = jbase + jj;
            if (j <= i || j >= KK) continue;
            float xx1 = fmaxf(ax1, sj[jj][0]);
            float yy1 = fmaxf(ay1, sj[jj][1]);
            float xx2 = fminf(ax2, sj[jj][2]);
            float yy2 = fminf(ay2, sj[jj][3]);
            float inter = fmaxf(xx2 - xx1, 0.0f)*fmaxf(yy2 - yy1, 0.0f);
            float den = fmaxf(areai + sj[jj][4] - inter, 1e-6f);
            if (inter / den > 0.6f) bits |= 1ull << jj;
        }
    }
    g_mask[(size_t)(n*KP + i)*16 + tj] = bits;
}

// ---------------- fused NMS scan + top-100 output + counter cleanup ----------------
// Warp-0-only scan with sparse fast path: per diag chunk, if no initially-alive bit
// is targeted by any initially-alive bit's mask (strictly-upper-triangular words),
// keep = alive0 and rem |= U with NO serial chain. Exact serial fallback otherwise.
// kb broadcast via shfl (no syncwarp, no shared staging in the loop).
__global__ void __launch_bounds__(256, 1) k_scanout(float* __restrict__ out, int out_size) {
    int n = blockIdx.x, t = threadIdx.x;
    __shared__ u32 keep_s[32];
    const u32* gm32 = (const u32*)g_mask;
    if (t < 32) {
        u32 rem = ~g_validw[n*32 + t];     // suppressed-or-invalid bits start set
        u32 m[32];
        {   // preload chunk 0: lane t takes word t of rows 0..31 (coalesced per row)
            const u32* rowbase = gm32 + ((size_t)(n*KP))*32 + t;
            #pragma unroll
            for (int b = 0; b < 32; b++) m[b] = rowbase[b*32];
        }
        for (int c = 0; c < 32; c++) {
            u32 mn[32];
            if (c < 31 && t >= c + 1) {
                // prefetch chunk c+1 (only lanes that will still use their column)
                const u32* rowbase = gm32 + ((size_t)(n*KP + (c + 1)*32))*32 + t;
                #pragma unroll
                for (int b = 0; b < 32; b++) mn[b] = rowbase[b*32];
            }
            u32 kbloc = 0;
            if (t == c) {
                u32 alive0 = ~rem;
                u32 U0 = 0, U1 = 0, U2 = 0, U3 = 0;
                #pragma unroll
                for (int b = 0; b < 32; b += 4) {
                    U0 |= m[b]     & (u32)(((int)(alive0 << (31 - b))) >> 31);
                    U1 |= m[b + 1] & (u32)(((int)(alive0 << (30 - b))) >> 31);
                    U2 |= m[b + 2] & (u32)(((int)(alive0 << (29 - b))) >> 31);
                    U3 |= m[b + 3] & (u32)(((int)(alive0 << (28 - b))) >> 31);
                }
                u32 U = (U0 | U1) | (U2 | U3);
                if ((U & alive0) == 0u) {
                    // no intra-chunk kill: exact shortcut
                    kbloc = alive0;
                    rem |= U;
                } else {
                    // exact serial fallback
                    u32 rcur = rem, kbv = 0;
                    #pragma unroll
                    for (int b = 0; b < 32; b++) {
                        u32 dead = (u32)(((int)(rcur << (31 - b))) >> 31);
                        kbv |= ~dead & (1u << b);
                        rcur |= m[b] & ~dead;
                    }
                    rem = rcur;
                    kbloc = kbv;
                }
                keep_s[c] = kbloc;
            }
            u32 kb = __shfl_sync(0xffffffffu, kbloc, c);
            if (t > c) {
                u32 A0 = 0, A1 = 0, A2 = 0, A3 = 0;
                #pragma unroll
                for (int b = 0; b < 32; b += 4) {
                    A0 |= m[b]     & (u32)(((int)(kb << (31 - b))) >> 31);
                    A1 |= m[b + 1] & (u32)(((int)(kb << (30 - b))) >> 31);
                    A2 |= m[b + 2] & (u32)(((int)(kb << (29 - b))) >> 31);
                    A3 |= m[b + 3] & (u32)(((int)(kb << (28 - b))) >> 31);
                }
                rem |= (A0 | A1) | (A2 | A3);
                #pragma unroll
                for (int b = 0; b < 32; b++) m[b] = mn[b];
            }
        }
    }
    __syncthreads();
    __shared__ int offs[32], noffs[32];
    __shared__ int cnts[32], ncnts[32];
    __shared__ int list[POST];
    __shared__ int mks;
    if (t < 32) {
        u32 vmask = (t == 31) ? 0xFFu : 0xFFFFFFFFu;   // bits i < 1000
        cnts[t]  = __popc(keep_s[t]);
        ncnts[t] = __popc(~keep_s[t] & vmask);
    }
    __syncthreads();
    if (t == 0) {
        int acc = 0;
        for (int w = 0; w < 32; w++) { offs[w] = acc; acc += cnts[w]; }
        mks = acc > POST ? POST : acc;
        int acc2 = 0;
        for (int w = 0; w < 32; w++) { noffs[w] = acc2; acc2 += ncnts[w]; }
    }
    __syncthreads();
    if (t < 32) {
        u32 w = keep_s[t];
        int off = offs[t];
        while (w && off < POST) { int b = __ffs(w) - 1; list[off++] = t*32 + b; w &= w - 1; }
        u32 vmask = (t == 31) ? 0xFFu : 0xFFFFFFFFu;
        u32 nw = ~keep_s[t] & vmask;
        int noff = mks + noffs[t];
        while (nw && noff < POST) { int b = __ffs(nw) - 1; list[noff++] = t*32 + b; nw &= nw - 1; }
    }
    __syncthreads();
    if (t < POST) {
        int j = list[t];
        bool ov = t < mks;
        int ob = (n*KP + j)*4;
        int base = n*POST*5 + t*5;
        if (base + 4 < out_size) {
            out[base]     = g_boxes[ob];
            out[base + 1] = g_boxes[ob + 1];
            out[base + 2] = g_boxes[ob + 2];
            out[base + 3] = g_boxes[ob + 3];
            out[base + 4] = ov ? g_score[n*KP + j] : 0.0f;
        }
        int lb = Nn*POST*5 + n*POST + t;
        if (lb < out_size) out[lb] = ov ? (float)g_label[n*KP + j] : 0.0f;
        int vb = Nn*POST*5 + Nn*POST + n*POST + t;
        if (vb < out_size) out[vb] = ov ? 1.0f : 0.0f;
    }
    // cleanup for next graph replay (deterministic: zero before, zero after)
    if (t >= 128 && t < 128 + FINE) g_fine[n*FINE + (t - 128)] = 0u;
    if (t == 224) { g_scnt[n] = 0; g_fbforce[n] = 0; }
}

extern "C" void kernel_launch(void* const* d_in, const int* in_sizes, int n_in,
                              void* d_out, int out_size) {
    const float* cls  = (const float*)d_in[0];
    const float* reg  = (const float*)d_in[1];
    const float* ctr  = (const float*)d_in[2];
    const float* pts  = (const float*)d_in[3];
    const float* imsz = (const float*)d_in[4];

    k_hist<<<dim3(250, 8), 256>>>(cls, ctr);
    k_sortdecode<<<8, 1024>>>(cls, ctr, reg, pts, imsz);
    k_mask<<<272, 256>>>();
    k_scanout<<<8, 256>>>((float*)d_out, out_size);
}

// round 15
// speedup vs baseline: 1.0694x; 1.0326x over previous
#include <cuda_runtime.h>
#include <cstdint>

typedef unsigned long long u64;
typedef unsigned int u32;

#define Nn 8
#define Cc 80
#define HWp 25600
#define PER_IMG (Cc*HWp)        // 2048000
#define FINE 64
#define FINE_BASE 8089          // (SPEC_BITS >> 17)
#define CAP 4096
#define CAP_SPEC 65536
#define KP 1024
#define KK 1000
#define POST 100
#define SPEC_BITS 0x3F333333u   /* bits of 0.70f */
#define REJECT_X 0.8400f        /* conservative: sigmoid(0.84)=0.6985 < 0.70 */
#define CSTAGE 4096
#define SSTAGE 512
#define TRI_JOBS 136            /* 16*17/2 tile pairs a<=b */
#define JOBS2 272               /* mask jobs + transpose jobs per image */
#define TCAP 224                /* T-rows gathered to shared (28KB) */

// ---------------- scratch (device globals; zero-init; counters re-zeroed by k_scanout) ----
__device__ u32   g_fine[Nn*FINE];
__device__ int   g_scnt[Nn];
__device__ int   g_fbforce[Nn];
__device__ u64   g_spec[Nn*CAP_SPEC];
__device__ float g_score[Nn*KP];
__device__ float g_boxes[Nn*KP*4];
__device__ int   g_label[Nn*KP];
__device__ u32   g_validw[Nn*32];
__device__ float g_maxo[Nn];
__device__ u64   g_mask[Nn*KP*16];
__device__ u64   g_maskT[Nn*KP*16];
__device__ u64   g_P[Nn*16];

__device__ __forceinline__ float sigmoidf_(float x) {
    return 1.0f / (1.0f + expf(-x));
}

// ---------------- pass 1: stream cls, warp-aggregated compact, dense sigmoid, fine hist ----
__global__ void __launch_bounds__(256) k_hist(const float* __restrict__ cls,
                                              const float* __restrict__ ctr) {
    __shared__ float sx[CSTAGE];
    __shared__ u32   se[CSTAGE];
    __shared__ u64   stage[SSTAGE];
    __shared__ u32   fine[FINE];
    __shared__ int cstage_n, sstage_n, sbase;
    if (threadIdx.x < FINE) fine[threadIdx.x] = 0;
    if (threadIdx.x == 0) { cstage_n = 0; sstage_n = 0; }
    __syncthreads();
    int n = blockIdx.y;
    u32 lane = threadIdx.x & 31;
    u32 lt_mask = (1u << lane) - 1u;
    const float4* cls4 = (const float4*)(cls + (size_t)n*PER_IMG);
    int t4 = blockIdx.x*2048 + threadIdx.x;
    // Phase A: stream + warp-aggregated compact
    #pragma unroll
    for (int it = 0; it < 8; it++, t4 += 256) {
        float4 x = cls4[t4];
        int e = t4*4;
        float pv[4] = {x.x, x.y, x.z, x.w};
        #pragma unroll
        for (int k = 0; k < 4; k++) {
            bool pred = (pv[k] >= REJECT_X);
            u32 ballot = __ballot_sync(0xffffffffu, pred);
            if (ballot) {
                int base;
                if (lane == 0) base = atomicAdd(&cstage_n, __popc(ballot));
                base = __shfl_sync(0xffffffffu, base, 0);
                if (pred) {
                    int pos = base + __popc(ballot & lt_mask);
                    if (pos < CSTAGE) { sx[pos] = pv[k]; se[pos] = (u32)(e + k); }
                }
            }
        }
    }
    __syncthreads();
    int m = cstage_n; if (m > CSTAGE) m = CSTAGE;
    // Phase B: dense sigmoid on compacted list
    const float* ctrn = ctr + n*HWp;
    for (int i = threadIdx.x; i < m; i += 256) {
        float xv = sx[i];
        u32 e = se[i];
        u32 c = e / (u32)HWp;
        u32 pix = e - c*(u32)HWp;
        float p = sigmoidf_(xv);
        float cv = sigmoidf_(ctrn[pix]);
        float s = p*cv;
        u32 sb = __float_as_uint(s);
        if (p > 0.05f && sb >= SPEC_BITS) {
            atomicAdd(&fine[(sb >> 17) - FINE_BASE], 1u);
            u64 key = (((u64)(~sb)) << 32) | (u64)(pix*80u + c);
            int pos = atomicAdd(&sstage_n, 1);
            if (pos < SSTAGE) stage[pos] = key;
            else {
                int gp = atomicAdd(&g_scnt[n], 1);
                if (gp < CAP_SPEC) g_spec[n*CAP_SPEC + gp] = key;
            }
        }
    }
    __syncthreads();
    if (threadIdx.x < FINE) {
        u32 v = fine[threadIdx.x];
        if (v) atomicAdd(&g_fine[n*FINE + threadIdx.x], v);
    }
    int sm = sstage_n < SSTAGE ? sstage_n : SSTAGE;
    if (threadIdx.x == 0 && sm > 0) sbase = atomicAdd(&g_scnt[n], sm);
    __syncthreads();
    for (int i = threadIdx.x; i < sm; i += 256) {
        int gp = sbase + i;
        if (gp < CAP_SPEC) g_spec[n*CAP_SPEC + gp] = stage[i];
    }
    if (threadIdx.x == 0 && cstage_n > CSTAGE) g_fbforce[n] = 1;
}

// ---------------- fused threshold + filter + bitonic sort + box decode + max_c ----------
__global__ void __launch_bounds__(1024) k_sortdecode(const float* __restrict__ cls,
                                                     const float* __restrict__ ctr,
                                                     const float* __restrict__ reg,
                                                     const float* __restrict__ pts,
                                                     const float* __restrict__ imsz) {
    __shared__ u64 sk[CAP];           // reused as u32[8192] hist in parachute
    __shared__ float red[1024];
    __shared__ int cnt_s;
    __shared__ int fb_s;
    __shared__ u32 tb_s;
    int n = blockIdx.x, tid = threadIdx.x;
    // threshold from fine histogram (fast path)
    if (tid == 0) {
        u32 cum = 0; int fstar = -1;
        for (int f = FINE - 1; f >= 1; f--) {
            cum += g_fine[n*FINE + f];
            if (cum >= (u32)KK) { fstar = f; break; }
        }
        int fb = (fstar < 0) || (g_scnt[n] > CAP_SPEC) || g_fbforce[n];
        fb_s = fb;
        tb_s = fb ? 0u : (((u32)(FINE_BASE + fstar)) << 17);
        cnt_s = 0;
    }
    __syncthreads();
    if (fb_s) {
        // parachute: exact full-range histogram using sk as u32[8192]
        u32* h = (u32*)sk;
        for (int i = tid; i < 8192; i += 1024) h[i] = 0;
        __syncthreads();
        const float* c0 = cls + (size_t)n*PER_IMG;
        const float* ctrn = ctr + n*HWp;
        for (int e = tid; e < PER_IMG; e += 1024) {
            int c = e / HWp; int pix = e - c*HWp;
            float p = sigmoidf_(c0[e]);
            if (p > 0.05f) {
                float cv = sigmoidf_(ctrn[pix]);
                u32 sb = __float_as_uint(p*cv);
                atomicAdd(&h[sb >> 17], 1u);
            }
        }
        __syncthreads();
        if (tid == 0) {
            u32 cum = 0; u32 tb = 0;
            for (int b = 8191; b >= 0; b--) {
                cum += h[b];
                if (cum >= (u32)KK) { tb = ((u32)b) << 17; break; }
            }
            tb_s = tb;
        }
        __syncthreads();
    }
    for (int i = tid; i < CAP; i += 1024) sk[i] = ~0ULL;
    __syncthreads();
    u32 tb = tb_s;
    if (!fb_s) {
        int m = g_scnt[n];
        for (int i = tid; i < m; i += 1024) {
            u64 key = g_spec[n*CAP_SPEC + i];
            u32 sb = ~((u32)(key >> 32));
            if (sb >= tb) {
                int pos = atomicAdd(&cnt_s, 1);
                if (pos < CAP) sk[pos] = key;
            }
        }
    } else {
        const float* c0 = cls + (size_t)n*PER_IMG;
        const float* ctrn = ctr + n*HWp;
        for (int e = tid; e < PER_IMG; e += 1024) {
            int c = e / HWp; int pix = e - c*HWp;
            float p = sigmoidf_(c0[e]);
            if (p > 0.05f) {
                float cv = sigmoidf_(ctrn[pix]);
                float s = p*cv;
                u32 sb = __float_as_uint(s);
                if (sb >= tb) {
                    int pos = atomicAdd(&cnt_s, 1);
                    if (pos < CAP) sk[pos] = (((u64)(~sb)) << 32) | (u64)((u32)pix*80u + (u32)c);
                }
            }
        }
    }
    __syncthreads();
    int cnt = cnt_s; if (cnt > CAP) cnt = CAP;
    int S = (cnt <= 2048) ? 2048 : 4096;
    for (int k2 = 2; k2 <= S; k2 <<= 1) {
        for (int j = k2 >> 1; j > 0; j >>= 1) {
            for (int i = tid; i < S; i += 1024) {
                int p = i ^ j;
                if (p > i) {
                    u64 a = sk[i], b = sk[p];
                    bool up = ((i & k2) == 0);
                    if ((a > b) == up) { sk[i] = b; sk[p] = a; }
                }
            }
            __syncthreads();
        }
    }
    float w1 = imsz[n*2] - 1.0f;
    float h1 = imsz[n*2 + 1] - 1.0f;
    const float* rg = reg + (size_t)n*4*HWp;
    float mx = 0.0f;
    {
        int r = tid;                       // KP == blockDim == 1024
        u64 key = sk[r];
        float val; int valid; u32 idx;
        if (key == ~0ULL || r >= KK) { val = -1.0f; valid = 0; idx = 0; }
        else {
            u32 sb = ~((u32)(key >> 32));
            val = __uint_as_float(sb);
            idx = (u32)key;
            valid = (val >= 0.0f) ? 1 : 0;
        }
        u32 c = idx % 80u;
        u32 loc = idx / 80u;
        float px = pts[loc*2], py = pts[loc*2 + 1];
        float d0 = rg[loc], d1 = rg[HWp + loc], d2 = rg[2*HWp + loc], d3 = rg[3*HWp + loc];
        float x1 = fminf(fmaxf(px - d0, 0.0f), w1);
        float y1 = fminf(fmaxf(py - d1, 0.0f), h1);
        float x2 = fminf(fmaxf(px + d2, 0.0f), w1);
        float y2 = fminf(fmaxf(py + d3, 0.0f), h1);
        int o = (n*KP + r)*4;
        g_boxes[o] = x1; g_boxes[o+1] = y1; g_boxes[o+2] = x2; g_boxes[o+3] = y2;
        g_label[n*KP + r] = (int)c + 1;
        g_score[n*KP + r] = valid ? sqrtf(fmaxf(val, 0.0f)) : -1.0f;
        // valid bitmap via ballot: 32 warps x 32 lanes = 1024 entries
        u32 bal = __ballot_sync(0xffffffffu, valid != 0);
        if ((tid & 31) == 0) g_validw[n*32 + (tid >> 5)] = bal;
        mx = valid ? fmaxf(fmaxf(x1, x2), fmaxf(y1, y2)) : 0.0f;
    }
    red[tid] = mx;
    __syncthreads();
    for (int s = 512; s > 0; s >>= 1) {
        if (tid < s) red[tid] = fmaxf(red[tid], red[tid + s]);
        __syncthreads();
    }
    if (tid == 0) g_maxo[n] = red[0] + 1.0f;
}

// ---------------- IoU tiles: mask jobs (j>i) + transpose jobs (j<i) + P union ----------
__global__ void __launch_bounds__(256) k_mask() {
    int jobLocal = threadIdx.x >> 6;       // 0..3
    int t = threadIdx.x & 63;
    int job = blockIdx.x*4 + jobLocal;     // 0..(8*JOBS2-1)
    int n = job / JOBS2;
    int q = job - n*JOBS2;
    int isT = (q >= TRI_JOBS);
    if (isT) q -= TRI_JOBS;
    int a = 0;
    for (int r = 0; r < 16; r++) {
        int cnt = 16 - r;
        if (q < cnt) { a = r; break; }
        q -= cnt;
    }
    int b = a + q;                          // a <= b
    int rT = isT ? b : a;                   // register-row tile
    int cT = isT ? a : b;                   // shared-col tile
    float maxo = g_maxo[n];
    int i = rT*64 + t;
    int oi = (n*KP + i)*4;
    float offi = (float)g_label[n*KP + i] * maxo;
    float ax1 = g_boxes[oi]   + offi;
    float ay1 = g_boxes[oi+1] + offi;
    float ax2 = g_boxes[oi+2] + offi;
    float ay2 = g_boxes[oi+3] + offi;
    float areai = (ax2 - ax1)*(ay2 - ay1);
    __shared__ float sb[4][64][5];
    int j0 = cT*64 + t;
    int oj = (n*KP + j0)*4;
    float offj = (float)g_label[n*KP + j0] * maxo;
    float bx1 = g_boxes[oj]   + offj;
    float by1 = g_boxes[oj+1] + offj;
    float bx2 = g_boxes[oj+2] + offj;
    float by2 = g_boxes[oj+3] + offj;
    sb[jobLocal][t][0] = bx1;
    sb[jobLocal][t][1] = by1;
    sb[jobLocal][t][2] = bx2;
    sb[jobLocal][t][3] = by2;
    sb[jobLocal][t][4] = (bx2 - bx1)*(by2 - by1);
    __syncthreads();
    u64 bits = 0;
    if (i < KK) {
        int jbase = cT*64;
        const float (*sj)[5] = sb[jobLocal];
        #pragma unroll 4
        for (int jj = 0; jj < 64; jj++) {
            int j = jbase + jj;
            bool ord = isT ? (j < i) : (j > i);
            if (!ord || j >= KK) continue;
            float xx1 = fmaxf(ax1, sj[jj][0]);
            float yy1 = fmaxf(ay1, sj[jj][1]);
            float xx2 = fminf(ax2, sj[jj][2]);
            float yy2 = fminf(ay2, sj[jj][3]);
            float inter = fmaxf(xx2 - xx1, 0.0f)*fmaxf(yy2 - yy1, 0.0f);
            float den = fmaxf(areai + sj[jj][4] - inter, 1e-6f);
            if (inter / den > 0.6f) bits |= 1ull << jj;
        }
    }
    if (isT) {
        g_maskT[(size_t)(n*KP + i)*16 + cT] = bits;
    } else {
        g_mask[(size_t)(n*KP + i)*16 + cT] = bits;
        // P union: OR of mask rows of VALID rows (warp-reduce, 1 atomic per warp)
        u32 vbit = (g_validw[n*32 + (i >> 5)] >> (i & 31)) & 1u;
        u64 v = vbit ? bits : 0ull;
        #pragma unroll
        for (int s = 16; s > 0; s >>= 1)
            v |= __shfl_down_sync(0xffffffffu, v, s);
        if ((t & 31) == 0 && v) atomicOr(&g_P[n*16 + cT], v);
    }
}

// ---------------- exact sparse NMS resolve + top-100 output + cleanup ----------------
// D = valid & P (rows possibly suppressed by SOME valid row). Rows outside D are
// provably kept (if valid). Only |D| rows resolved serially via transpose rows
// (suppressor bitsets), each checked against the finalized keep map. Exact greedy.
__global__ void __launch_bounds__(256, 1) k_scanout(float* __restrict__ out, int out_size) {
    int n = blockIdx.x, t = threadIdx.x;
    __shared__ u32 km[32];              // keep map (final)
    __shared__ u32 Dw[32];
    __shared__ int dlist[KP];
    __shared__ int dcnt_s;
    __shared__ u32 Trows[TCAP][32];     // 28KB gathered transpose rows
    const u32* gmT32 = (const u32*)g_maskT;
    const u32* P32 = (const u32*)g_P;
    if (t < 32) {
        u32 valid = g_validw[n*32 + t];
        Dw[t] = valid & P32[n*32 + t];
        km[t] = valid;
    }
    __syncthreads();
    if (t == 0) {
        int cnt = 0;
        for (int w = 0; w < 32; w++) {
            u32 d = Dw[w];
            while (d) { int bb = __ffs(d) - 1; dlist[cnt++] = w*32 + bb; d &= d - 1; }
        }
        dcnt_s = cnt;
    }
    __syncthreads();
    int dcnt = dcnt_s;
    int gcap = dcnt < TCAP ? dcnt : TCAP;
    for (int q = t; q < gcap*32; q += 256) {
        int k = q >> 5, w = q & 31;
        Trows[k][w] = gmT32[((size_t)(n*KP + dlist[k]))*32 + w];
    }
    __syncthreads();
    if (t == 0) {
        for (int k = 0; k < dcnt; k++) {
            int d = dlist[k];
            int wl = (d >> 5) | 1;          // valid T words: 0..wl (upper words stale)
            u32 acc = 0;
            if (k < TCAP) {
                #pragma unroll
                for (int w = 0; w < 32; w++) {
                    u32 sel = (w <= wl) ? 0xFFFFFFFFu : 0u;
                    acc |= Trows[k][w] & km[w] & sel;
                }
            } else {
                const u32* Tr = gmT32 + ((size_t)(n*KP + d))*32;
                for (int w = 0; w <= wl; w++) acc |= Tr[w] & km[w];
            }
            if (acc) km[d >> 5] &= ~(1u << (d & 31));
        }
    }
    __syncthreads();
    __shared__ int offs[32], noffs[32];
    __shared__ int cnts[32], ncnts[32];
    __shared__ int list[POST];
    __shared__ int mks;
    if (t < 32) {
        u32 vmask = (t == 31) ? 0xFFu : 0xFFFFFFFFu;   // bits i < 1000
        cnts[t]  = __popc(km[t]);
        ncnts[t] = __popc(~km[t] & vmask);
    }
    __syncthreads();
    if (t == 0) {
        int acc = 0;
        for (int w = 0; w < 32; w++) { offs[w] = acc; acc += cnts[w]; }
        mks = acc > POST ? POST : acc;
        int acc2 = 0;
        for (int w = 0; w < 32; w++) { noffs[w] = acc2; acc2 += ncnts[w]; }
    }
    __syncthreads();
    if (t < 32) {
        u32 w = km[t];
        int off = offs[t];
        while (w && off < POST) { int bb = __ffs(w) - 1; list[off++] = t*32 + bb; w &= w - 1; }
        u32 vmask = (t == 31) ? 0xFFu : 0xFFFFFFFFu;
        u32 nw = ~km[t] & vmask;
        int noff = mks + noffs[t];
        while (nw && noff < POST) { int bb = __ffs(nw) - 1; list[noff++] = t*32 + bb; nw &= nw - 1; }
    }
    __syncthreads();
    if (t < POST) {
        int j = list[t];
        bool ov = t < mks;
        int ob = (n*KP + j)*4;
        int base = n*POST*5 + t*5;
        if (base + 4 < out_size) {
            out[base]     = g_boxes[ob];
            out[base + 1] = g_boxes[ob + 1];
            out[base + 2] = g_boxes[ob + 2];
            out[base + 3] = g_boxes[ob + 3];
            out[base + 4] = ov ? g_score[n*KP + j] : 0.0f;
        }
        int lb = Nn*POST*5 + n*POST + t;
        if (lb < out_size) out[lb] = ov ? (float)g_label[n*KP + j] : 0.0f;
        int vb = Nn*POST*5 + Nn*POST + n*POST + t;
        if (vb < out_size) out[vb] = ov ? 1.0f : 0.0f;
    }
    // cleanup for next graph replay (deterministic: zero before, zero after)
    if (t >= 128 && t < 128 + FINE) g_fine[n*FINE + (t - 128)] = 0u;
    if (t >= 192 && t < 208) g_P[n*16 + (t - 192)] = 0ull;
    if (t == 224) { g_scnt[n] = 0; g_fbforce[n] = 0; }
}

extern "C" void kernel_launch(void* const* d_in, const int* in_sizes, int n_in,
                              void* d_out, int out_size) {
    const float* cls  = (const float*)d_in[0];
    const float* reg  = (const float*)d_in[1];
    const float* ctr  = (const float*)d_in[2];
    const float* pts  = (const float*)d_in[3];
    const float* imsz = (const float*)d_in[4];

    k_hist<<<dim3(250, 8), 256>>>(cls, ctr);
    k_sortdecode<<<8, 1024>>>(cls, ctr, reg, pts, imsz);
    k_mask<<<(Nn*JOBS2)/4, 256>>>();
    k_scanout<<<8, 256>>>((float*)d_out, out_size);
}

// round 17
// speedup vs baseline: 1.1596x; 1.0843x over previous
#include <cuda_runtime.h>
#include <cstdint>

typedef unsigned long long u64;
typedef unsigned int u32;

#define Nn 8
#define Cc 80
#define HWp 25600
#define PER_IMG (Cc*HWp)        // 2048000
#define FINE 64
#define FINE_BASE 8089          // (SPEC_BITS >> 17)
#define CAP 4096
#define CAP_SPEC 65536
#define KP 1024
#define KK 1000
#define POST 100
#define SPEC_BITS 0x3F333333u   /* bits of 0.70f */
#define REJECT_X 0.8400f        /* conservative: sigmoid(0.84)=0.6985 < 0.70 */
#define CSTAGE 4096
#define SSTAGE 512
#define TILE_JOBS 136           /* 16*17/2 upper-triangular 64x64 tiles */
#define CCAP 128                /* C rows resolved via shared bit-matrix */

// ---------------- scratch (device globals; zero-init; counters re-zeroed by k_scanout) ----
__device__ u32   g_fine[Nn*FINE];
__device__ int   g_scnt[Nn];
__device__ int   g_fbforce[Nn];
__device__ u64   g_spec[Nn*CAP_SPEC];
__device__ float g_score[Nn*KP];
__device__ float g_boxes[Nn*KP*4];
__device__ int   g_label[Nn*KP];
__device__ u32   g_validw[Nn*32];
__device__ float g_maxo[Nn];
__device__ u64   g_mask[Nn*KP*16];

__device__ __forceinline__ float sigmoidf_(float x) {
    return 1.0f / (1.0f + expf(-x));
}

// ---------------- pass 1: stream cls, warp-aggregated compact, dense sigmoid, fine hist ----
__global__ void __launch_bounds__(256) k_hist(const float* __restrict__ cls,
                                              const float* __restrict__ ctr) {
    __shared__ float sx[CSTAGE];
    __shared__ u32   se[CSTAGE];
    __shared__ u64   stage[SSTAGE];
    __shared__ u32   fine[FINE];
    __shared__ int cstage_n, sstage_n, sbase;
    if (threadIdx.x < FINE) fine[threadIdx.x] = 0;
    if (threadIdx.x == 0) { cstage_n = 0; sstage_n = 0; }
    __syncthreads();
    int n = blockIdx.y;
    u32 lane = threadIdx.x & 31;
    u32 lt_mask = (1u << lane) - 1u;
    const float4* cls4 = (const float4*)(cls + (size_t)n*PER_IMG);
    int t4 = blockIdx.x*2048 + threadIdx.x;
    // Phase A: stream + warp-aggregated compact
    #pragma unroll
    for (int it = 0; it < 8; it++, t4 += 256) {
        float4 x = cls4[t4];
        int e = t4*4;
        float pv[4] = {x.x, x.y, x.z, x.w};
        #pragma unroll
        for (int k = 0; k < 4; k++) {
            bool pred = (pv[k] >= REJECT_X);
            u32 ballot = __ballot_sync(0xffffffffu, pred);
            if (ballot) {
                int base;
                if (lane == 0) base = atomicAdd(&cstage_n, __popc(ballot));
                base = __shfl_sync(0xffffffffu, base, 0);
                if (pred) {
                    int pos = base + __popc(ballot & lt_mask);
                    if (pos < CSTAGE) { sx[pos] = pv[k]; se[pos] = (u32)(e + k); }
                }
            }
        }
    }
    __syncthreads();
    int m = cstage_n; if (m > CSTAGE) m = CSTAGE;
    // Phase B: dense sigmoid on compacted list
    const float* ctrn = ctr + n*HWp;
    for (int i = threadIdx.x; i < m; i += 256) {
        float xv = sx[i];
        u32 e = se[i];
        u32 c = e / (u32)HWp;
        u32 pix = e - c*(u32)HWp;
        float p = sigmoidf_(xv);
        float cv = sigmoidf_(ctrn[pix]);
        float s = p*cv;
        u32 sb = __float_as_uint(s);
        if (p > 0.05f && sb >= SPEC_BITS) {
            atomicAdd(&fine[(sb >> 17) - FINE_BASE], 1u);
            u64 key = (((u64)(~sb)) << 32) | (u64)(pix*80u + c);
            int pos = atomicAdd(&sstage_n, 1);
            if (pos < SSTAGE) stage[pos] = key;
            else {
                int gp = atomicAdd(&g_scnt[n], 1);
                if (gp < CAP_SPEC) g_spec[n*CAP_SPEC + gp] = key;
            }
        }
    }
    __syncthreads();
    if (threadIdx.x < FINE) {
        u32 v = fine[threadIdx.x];
        if (v) atomicAdd(&g_fine[n*FINE + threadIdx.x], v);
    }
    int sm = sstage_n < SSTAGE ? sstage_n : SSTAGE;
    if (threadIdx.x == 0 && sm > 0) sbase = atomicAdd(&g_scnt[n], sm);
    __syncthreads();
    for (int i = threadIdx.x; i < sm; i += 256) {
        int gp = sbase + i;
        if (gp < CAP_SPEC) g_spec[n*CAP_SPEC + gp] = stage[i];
    }
    if (threadIdx.x == 0 && cstage_n > CSTAGE) g_fbforce[n] = 1;
}

// ---------------- fused threshold + filter + bitonic sort + box decode + max_c ----------
__global__ void __launch_bounds__(1024) k_sortdecode(const float* __restrict__ cls,
                                                     const float* __restrict__ ctr,
                                                     const float* __restrict__ reg,
                                                     const float* __restrict__ pts,
                                                     const float* __restrict__ imsz) {
    __shared__ u64 sk[CAP];           // reused as u32[8192] hist in parachute
    __shared__ float red[1024];
    __shared__ int cnt_s;
    __shared__ int fb_s;
    __shared__ u32 tb_s;
    int n = blockIdx.x, tid = threadIdx.x;
    // threshold from fine histogram (fast path)
    if (tid == 0) {
        u32 cum = 0; int fstar = -1;
        for (int f = FINE - 1; f >= 1; f--) {
            cum += g_fine[n*FINE + f];
            if (cum >= (u32)KK) { fstar = f; break; }
        }
        int fb = (fstar < 0) || (g_scnt[n] > CAP_SPEC) || g_fbforce[n];
        fb_s = fb;
        tb_s = fb ? 0u : (((u32)(FINE_BASE + fstar)) << 17);
        cnt_s = 0;
    }
    __syncthreads();
    if (fb_s) {
        // parachute: exact full-range histogram using sk as u32[8192]
        u32* h = (u32*)sk;
        for (int i = tid; i < 8192; i += 1024) h[i] = 0;
        __syncthreads();
        const float* c0 = cls + (size_t)n*PER_IMG;
        const float* ctrn = ctr + n*HWp;
        for (int e = tid; e < PER_IMG; e += 1024) {
            int c = e / HWp; int pix = e - c*HWp;
            float p = sigmoidf_(c0[e]);
            if (p > 0.05f) {
                float cv = sigmoidf_(ctrn[pix]);
                u32 sb = __float_as_uint(p*cv);
                atomicAdd(&h[sb >> 17], 1u);
            }
        }
        __syncthreads();
        if (tid == 0) {
            u32 cum = 0; u32 tb = 0;
            for (int b = 8191; b >= 0; b--) {
                cum += h[b];
                if (cum >= (u32)KK) { tb = ((u32)b) << 17; break; }
            }
            tb_s = tb;
        }
        __syncthreads();
    }
    for (int i = tid; i < CAP; i += 1024) sk[i] = ~0ULL;
    __syncthreads();
    u32 tb = tb_s;
    if (!fb_s) {
        int m = g_scnt[n];
        for (int i = tid; i < m; i += 1024) {
            u64 key = g_spec[n*CAP_SPEC + i];
            u32 sb = ~((u32)(key >> 32));
            if (sb >= tb) {
                int pos = atomicAdd(&cnt_s, 1);
                if (pos < CAP) sk[pos] = key;
            }
        }
    } else {
        const float* c0 = cls + (size_t)n*PER_IMG;
        const float* ctrn = ctr + n*HWp;
        for (int e = tid; e < PER_IMG; e += 1024) {
            int c = e / HWp; int pix = e - c*HWp;
            float p = sigmoidf_(c0[e]);
            if (p > 0.05f) {
                float cv = sigmoidf_(ctrn[pix]);
                float s = p*cv;
                u32 sb = __float_as_uint(s);
                if (sb >= tb) {
                    int pos = atomicAdd(&cnt_s, 1);
                    if (pos < CAP) sk[pos] = (((u64)(~sb)) << 32) | (u64)((u32)pix*80u + (u32)c);
                }
            }
        }
    }
    __syncthreads();
    int cnt = cnt_s; if (cnt > CAP) cnt = CAP;
    int S = (cnt <= 2048) ? 2048 : 4096;
    for (int k2 = 2; k2 <= S; k2 <<= 1) {
        for (int j = k2 >> 1; j > 0; j >>= 1) {
            for (int i = tid; i < S; i += 1024) {
                int p = i ^ j;
                if (p > i) {
                    u64 a = sk[i], b = sk[p];
                    bool up = ((i & k2) == 0);
                    if ((a > b) == up) { sk[i] = b; sk[p] = a; }
                }
            }
            __syncthreads();
        }
    }
    float w1 = imsz[n*2] - 1.0f;
    float h1 = imsz[n*2 + 1] - 1.0f;
    const float* rg = reg + (size_t)n*4*HWp;
    float mx = 0.0f;
    {
        int r = tid;                       // KP == blockDim == 1024
        u64 key = sk[r];
        float val; int valid; u32 idx;
        if (key == ~0ULL || r >= KK) { val = -1.0f; valid = 0; idx = 0; }
        else {
            u32 sb = ~((u32)(key >> 32));
            val = __uint_as_float(sb);
            idx = (u32)key;
            valid = (val >= 0.0f) ? 1 : 0;
        }
        u32 c = idx % 80u;
        u32 loc = idx / 80u;
        float px = pts[loc*2], py = pts[loc*2 + 1];
        float d0 = rg[loc], d1 = rg[HWp + loc], d2 = rg[2*HWp + loc], d3 = rg[3*HWp + loc];
        float x1 = fminf(fmaxf(px - d0, 0.0f), w1);
        float y1 = fminf(fmaxf(py - d1, 0.0f), h1);
        float x2 = fminf(fmaxf(px + d2, 0.0f), w1);
        float y2 = fminf(fmaxf(py + d3, 0.0f), h1);
        int o = (n*KP + r)*4;
        g_boxes[o] = x1; g_boxes[o+1] = y1; g_boxes[o+2] = x2; g_boxes[o+3] = y2;
        g_label[n*KP + r] = (int)c + 1;
        g_score[n*KP + r] = valid ? sqrtf(fmaxf(val, 0.0f)) : -1.0f;
        // valid bitmap via ballot: 32 warps x 32 lanes = 1024 entries
        u32 bal = __ballot_sync(0xffffffffu, valid != 0);
        if ((tid & 31) == 0) g_validw[n*32 + (tid >> 5)] = bal;
        mx = valid ? fmaxf(fmaxf(x1, x2), fmaxf(y1, y2)) : 0.0f;
    }
    red[tid] = mx;
    __syncthreads();
    for (int s = 512; s > 0; s >>= 1) {
        if (tid < s) red[tid] = fmaxf(red[tid], red[tid + s]);
        __syncthreads();
    }
    if (tid == 0) g_maxo[n] = red[0] + 1.0f;
}

// ---------------- dense triangular IoU tiles: 4 tile-jobs per 256-thread block ----------
__global__ void __launch_bounds__(256) k_mask() {
    int jobLocal = threadIdx.x >> 6;       // 0..3
    int t = threadIdx.x & 63;
    int job = blockIdx.x*4 + jobLocal;     // 0..1087
    int n = job / TILE_JOBS;
    int q = job - n*TILE_JOBS;
    int ti = 0;
    for (int r = 0; r < 16; r++) {
        int cnt = 16 - r;
        if (q < cnt) { ti = r; break; }
        q -= cnt;
    }
    int tj = ti + q;
    float maxo = g_maxo[n];
    int i = ti*64 + t;
    int oi = (n*KP + i)*4;
    float offi = (float)g_label[n*KP + i] * maxo;
    float ax1 = g_boxes[oi]   + offi;
    float ay1 = g_boxes[oi+1] + offi;
    float ax2 = g_boxes[oi+2] + offi;
    float ay2 = g_boxes[oi+3] + offi;
    float areai = (ax2 - ax1)*(ay2 - ay1);
    __shared__ float sb[4][64][5];
    int j0 = tj*64 + t;
    int oj = (n*KP + j0)*4;
    float offj = (float)g_label[n*KP + j0] * maxo;
    float bx1 = g_boxes[oj]   + offj;
    float by1 = g_boxes[oj+1] + offj;
    float bx2 = g_boxes[oj+2] + offj;
    float by2 = g_boxes[oj+3] + offj;
    sb[jobLocal][t][0] = bx1;
    sb[jobLocal][t][1] = by1;
    sb[jobLocal][t][2] = bx2;
    sb[jobLocal][t][3] = by2;
    sb[jobLocal][t][4] = (bx2 - bx1)*(by2 - by1);
    __syncthreads();
    u64 bits = 0;
    if (i < KK) {
        int jbase = tj*64;
        const float (*sj)[5] = sb[jobLocal];
        #pragma unroll 4
        for (int jj = 0; jj < 64; jj++) {
            int j = jbase + jj;
            if (j <= i || j >= KK) continue;
            float xx1 = fmaxf(ax1, sj[jj][0]);
            float yy1 = fmaxf(ay1, sj[jj][1]);
            float xx2 = fminf(ax2, sj[jj][2]);
            float yy2 = fminf(ay2, sj[jj][3]);
            float inter = fmaxf(xx2 - xx1, 0.0f)*fmaxf(yy2 - yy1, 0.0f);
            float den = fmaxf(areai + sj[jj][4] - inter, 1e-6f);
            if (inter / den > 0.6f) bits |= 1ull << jj;
        }
    }
    g_mask[(size_t)(n*KP + i)*16 + tj] = bits;
}

// ---------------- exact sparse NMS from M alone + top-100 output + cleanup ----------------
// S_all = OR of M-rows over valid rows; C = valid & S_all (possibly-killed superset).
// Rows outside C: kept iff valid (exact). S0 = OR over valid non-C rows (all kept) ->
// killed0. C-C interactions resolved via parallel bit-matrix + ~|C|-step scalar loop.
__global__ void __launch_bounds__(512, 1) k_scanout(float* __restrict__ out, int out_size) {
    int n = blockIdx.x, t = threadIdx.x;
    __shared__ u32 vw[32], Sw[32], Cw[32], S0[32], km[32];
    __shared__ u32 part[16][32];
    __shared__ int dlist[KP];
    __shared__ int dcnt_s;
    __shared__ u32 MC[CCAP][32];
    __shared__ u64 Bsh[CCAP][2];
    const u32* gm32 = (const u32*)g_mask;
    if (t < 32) vw[t] = g_validw[n*32 + t];
    __syncthreads();
    int wlane = t & 31, rg = t >> 5;       // 16 row-groups x 32 word-lanes
    // pass 1: S_all over valid rows (coalesced: 32 lanes cover one row's words)
    u32 acc = 0;
    for (int r = rg; r < KP; r += 16) {
        u32 vb = (vw[r >> 5] >> (r & 31)) & 1u;
        u32 mw = gm32[((size_t)(n*KP + r))*32 + wlane];
        acc |= (0u - vb) & mw;
    }
    part[rg][wlane] = acc;
    __syncthreads();
    if (t < 32) {
        u32 s = 0;
        #pragma unroll
        for (int k = 0; k < 16; k++) s |= part[k][t];
        Sw[t] = s; Cw[t] = s & vw[t]; km[t] = vw[t];
    }
    __syncthreads();
    // pass 2: S0 over valid & ~C rows (all definitely kept)
    acc = 0;
    for (int r = rg; r < KP; r += 16) {
        u32 vb = ((vw[r >> 5] & ~Cw[r >> 5]) >> (r & 31)) & 1u;
        u32 mw = gm32[((size_t)(n*KP + r))*32 + wlane];
        acc |= (0u - vb) & mw;
    }
    __syncthreads();
    part[rg][wlane] = acc;
    __syncthreads();
    if (t < 32) {
        u32 s = 0;
        #pragma unroll
        for (int k = 0; k < 16; k++) s |= part[k][t];
        S0[t] = s;
    }
    if (t == 32) {
        int cnt = 0;
        for (int w = 0; w < 32; w++) {
            u32 d = Cw[w];
            while (d) { int bb = __ffs(d) - 1; dlist[cnt++] = w*32 + bb; d &= d - 1; }
        }
        dcnt_s = cnt;
    }
    __syncthreads();
    int dcnt = dcnt_s;
    if (dcnt <= CCAP) {
        for (int q = t; q < dcnt*32; q += 512)
            MC[q >> 5][q & 31] = gm32[((size_t)(n*KP + dlist[q >> 5]))*32 + (q & 31)];
        __syncthreads();
        if (t < dcnt) {
            int c2 = dlist[t]; int w2 = c2 >> 5; u32 b2 = 1u << (c2 & 31);
            u64 B0 = 0, B1 = 0;
            for (int k1 = 0; k1 < t; k1++) {
                u64 bit = (MC[k1][w2] & b2) ? 1ull : 0ull;
                if (k1 < 64) B0 |= bit << k1; else B1 |= bit << (k1 - 64);
            }
            Bsh[t][0] = B0; Bsh[t][1] = B1;
        }
        __syncthreads();
        if (t == 0) {
            u64 kept0 = 0, kept1 = 0;
            for (int k = 0; k < dcnt; k++) {
                int c = dlist[k];
                u32 k0 = (S0[c >> 5] >> (c & 31)) & 1u;
                bool killed = (k0 != 0u) || (((Bsh[k][0] & kept0) | (Bsh[k][1] & kept1)) != 0ull);
                if (killed) km[c >> 5] &= ~(1u << (c & 31));
                else { if (k < 64) kept0 |= 1ull << k; else kept1 |= 1ull << (k - 64); }
            }
        }
    } else {
        // exact global fallback (never expected on this data)
        if (t == 0) {
            for (int k = 0; k < dcnt; k++) {
                int c = dlist[k];
                u32 k0 = (S0[c >> 5] >> (c & 31)) & 1u;
                bool killed = (k0 != 0u);
                for (int k1 = 0; k1 < k && !killed; k1++) {
                    int c1 = dlist[k1];
                    if ((km[c1 >> 5] >> (c1 & 31)) & 1u) {
                        u32 mw = gm32[((size_t)(n*KP + c1))*32 + (c >> 5)];
                        if ((mw >> (c & 31)) & 1u) killed = true;
                    }
                }
                if (killed) km[c >> 5] &= ~(1u << (c & 31));
            }
        }
    }
    __syncthreads();
    __shared__ int offs[32], noffs[32];
    __shared__ int cnts[32], ncnts[32];
    __shared__ int list[POST];
    __shared__ int mks;
    if (t < 32) {
        u32 vmask = (t == 31) ? 0xFFu : 0xFFFFFFFFu;   // bits i < 1000
        cnts[t]  = __popc(km[t]);
        ncnts[t] = __popc(~km[t] & vmask);
    }
    __syncthreads();
    if (t == 0) {
        int a = 0;
        for (int w = 0; w < 32; w++) { offs[w] = a; a += cnts[w]; }
        mks = a > POST ? POST : a;
        int a2 = 0;
        for (int w = 0; w < 32; w++) { noffs[w] = a2; a2 += ncnts[w]; }
    }
    __syncthreads();
    if (t < 32) {
        u32 w = km[t];
        int off = offs[t];
        while (w && off < POST) { int bb = __ffs(w) - 1; list[off++] = t*32 + bb; w &= w - 1; }
        u32 vmask = (t == 31) ? 0xFFu : 0xFFFFFFFFu;
        u32 nw = ~km[t] & vmask;
        int noff = mks + noffs[t];
        while (nw && noff < POST) { int bb = __ffs(nw) - 1; list[noff++] = t*32 + bb; nw &= nw - 1; }
    }
    __syncthreads();
    if (t < POST) {
        int j = list[t];
        bool ov = t < mks;
        int ob = (n*KP + j)*4;
        int base = n*POST*5 + t*5;
        if (base + 4 < out_size) {
            out[base]     = g_boxes[ob];
            out[base + 1] = g_boxes[ob + 1];
            out[base + 2] = g_boxes[ob + 2];
            out[base + 3] = g_boxes[ob + 3];
            out[base + 4] = ov ? g_score[n*KP + j] : 0.0f;
        }
        int lb = Nn*POST*5 + n*POST + t;
        if (lb < out_size) out[lb] = ov ? (float)g_label[n*KP + j] : 0.0f;
        int vb = Nn*POST*5 + Nn*POST + n*POST + t;
        if (vb < out_size) out[vb] = ov ? 1.0f : 0.0f;
    }
    // cleanup for next graph replay (deterministic: zero before, zero after)
    if (t >= 128 && t < 128 + FINE) g_fine[n*FINE + (t - 128)] = 0u;
    if (t == 224) { g_scnt[n] = 0; g_fbforce[n] = 0; }
}

extern "C" void kernel_launch(void* const* d_in, const int* in_sizes, int n_in,
                              void* d_out, int out_size) {
    const float* cls  = (const float*)d_in[0];
    const float* reg  = (const float*)d_in[1];
    const float* ctr  = (const float*)d_in[2];
    const float* pts  = (const float*)d_in[3];
    const float* imsz = (const float*)d_in[4];

    k_hist<<<dim3(250, 8), 256>>>(cls, ctr);
    k_sortdecode<<<8, 1024>>>(cls, ctr, reg, pts, imsz);
    k_mask<<<272, 256>>>();
    k_scanout<<<8, 512>>>((float*)d_out, out_size);
}